// round 8
// baseline (speedup 1.0000x reference)
#include <cuda_runtime.h>
#include <cuda_fp16.h>
#include <cstdint>

#define H_  32
#define SQ_ 2048
#define SK_ 2048
#define DH_ 128
#define QT  128          // q rows per CTA
#define KT  32           // k per chunk
#define NCH (SK_/KT)     // 64 chunks
#define NV  4            // V pipeline stages

// SMEM layout (dynamic):
#define VSTAGE  8192                      // 32k x 128d fp16, xor-swizzled
#define OFF_P   (NV * VSTAGE)             // 32768
#define OFF_SUM (OFF_P + 2 * 8192)        // 49152
#define SMEM_SZ (OFF_SUM + 512)           // 49664

// V converted to fp16, natural [h][k][d] layout
__device__ alignas(16) __half g_vh[(size_t)H_ * SK_ * DH_];

__device__ __forceinline__ uint32_t smem_u32(const void* p) {
    uint32_t a;
    asm("{ .reg .u64 t; cvta.to.shared.u64 t, %1; cvt.u32.u64 %0, t; }" : "=r"(a) : "l"(p));
    return a;
}

#define MMA16816(D, A, B0, B1) \
    asm volatile( \
        "mma.sync.aligned.m16n8k16.row.col.f32.f16.f16.f32 " \
        "{%0,%1,%2,%3}, {%4,%5,%6,%7}, {%8,%9}, {%0,%1,%2,%3};" \
        : "+f"((D)[0]), "+f"((D)[1]), "+f"((D)[2]), "+f"((D)[3]) \
        : "r"((A)[0]), "r"((A)[1]), "r"((A)[2]), "r"((A)[3]), \
          "r"(B0), "r"(B1))

// ---------------- V fp32 -> fp16 convert ----------------
__global__ void convert_v_kernel(const float* __restrict__ v) {
    size_t i = ((size_t)blockIdx.x * 256 + threadIdx.x) * 8;
    float4 a = *(const float4*)(v + i);
    float4 b = *(const float4*)(v + i + 4);
    __half2 h0 = __floats2half2_rn(a.x, a.y);
    __half2 h1 = __floats2half2_rn(a.z, a.w);
    __half2 h2 = __floats2half2_rn(b.x, b.y);
    __half2 h3 = __floats2half2_rn(b.z, b.w);
    uint4 o;
    o.x = *(uint32_t*)&h0; o.y = *(uint32_t*)&h1;
    o.z = *(uint32_t*)&h2; o.w = *(uint32_t*)&h3;
    *(uint4*)(g_vh + i) = o;
}

// ---------------- Main fused kernel ----------------
// 256 threads = 8 warps. Warp w: q rows [32*(w&3), +32), n cols [64*(w>>2), +64).
__global__ void __launch_bounds__(256, 2)
attn_sink_kernel(const float* __restrict__ logits,
                 const float* __restrict__ sinks,
                 float* __restrict__ out)
{
    extern __shared__ char smem[];
    float* rowsum = (float*)(smem + OFF_SUM);

    const int tid = threadIdx.x;
    const int w   = tid >> 5;
    const int l   = tid & 31;
    const int h   = blockIdx.x >> 4;
    const int q0  = (blockIdx.x & 15) * QT;

    const int qw = w & 3;      // q 32-group
    const int nh = w >> 2;     // n 64-half
    const int g  = l >> 2;     // acc row group
    const int m  = l & 3;      // acc col pair
    const int lu = l >> 4;
    const int kl = (l & 7) + 8 * ((l >> 3) & 1);

    // exp-phase mapping: thread -> (row, k-half)
    const int er  = tid >> 1;
    const int eh  = tid & 1;
    const int esp = ((er >> 1) ^ (er >> 3)) & 3;   // P store swizzle

    const float*  Lrow = logits + ((size_t)h * SQ_ + q0 + er) * SK_ + eh * 16;
    const __half* Vh   = g_vh + (size_t)h * SK_ * DH_;
    const uint32_t vb  = smem_u32(smem);
    const uint32_t pbu = vb + OFF_P;

    // A-ldmatrix precomputed per-mtile base/swizzle
    uint32_t pA[2], spA[2];
#pragma unroll
    for (int mt = 0; mt < 2; mt++) {
        int R = 32 * qw + 16 * mt + kl;
        pA[mt]  = pbu + (uint32_t)(R * 64);
        spA[mt] = (uint32_t)(((R >> 1) ^ (R >> 3)) & 3);
    }
    // B-ldmatrix precomputed per-ntile offsets
    uint32_t uB[4];
#pragma unroll
    for (int nt = 0; nt < 4; nt++) {
        int u = 8 * nh + 2 * nt + lu;
        uB[nt] = (uint32_t)(((u >> 3) << 12) + (((u & 7) ^ (l & 7)) << 4));
    }

    float acc[2][8][4];
#pragma unroll
    for (int mt = 0; mt < 2; mt++)
#pragma unroll
        for (int nt = 0; nt < 8; nt++)
#pragma unroll
            for (int c = 0; c < 4; c++) acc[mt][nt][c] = 0.f;
    float psum = 0.f;

    // V chunk loader: 32k x 16 granules = 512 / 256 thr = 2 each
    auto load_V = [&](int c) {
        const int s = c & (NV - 1);
#pragma unroll
        for (int u = 0; u < 2; u++) {
            int ci = u * 256 + tid;
            int k = ci >> 4, d = (ci & 15) * 8;
            uint32_t dst = vb + (uint32_t)(s * VSTAGE) + (uint32_t)((d >> 6) << 12)
                         + (uint32_t)(k << 7)
                         + (uint32_t)((((d >> 3) & 7) ^ (k & 7)) << 4);
            const __half* src = Vh + (size_t)(c * KT + k) * DH_ + d;
            asm volatile("cp.async.cg.shared.global [%0], [%1], 16;" :: "r"(dst), "l"(src));
        }
    };

    // MMA over one chunk: P[pb] x V[stage]
    auto mma_chunk = [&](int pb, int vs) {
        const uint32_t vst   = vb + (uint32_t)(vs * VSTAGE);
        const uint32_t pboff = (uint32_t)(pb * 8192);
#pragma unroll
        for (int j = 0; j < 2; j++) {
            uint32_t a[2][4];
#pragma unroll
            for (int mt = 0; mt < 2; mt++) {
                uint32_t pa = pA[mt] + pboff + ((((uint32_t)(lu + 2 * j)) ^ spA[mt]) << 4);
                asm volatile(
                    "ldmatrix.sync.aligned.m8n8.x4.shared.b16 {%0,%1,%2,%3}, [%4];"
                    : "=r"(a[mt][0]), "=r"(a[mt][1]), "=r"(a[mt][2]), "=r"(a[mt][3])
                    : "r"(pa));
            }
            uint32_t b[4][4];
            const uint32_t rowoff = (uint32_t)((16 * j + kl) << 7);
#pragma unroll
            for (int nt = 0; nt < 4; nt++) {
                uint32_t va = vst + uB[nt] + rowoff;
                asm volatile(
                    "ldmatrix.sync.aligned.m8n8.x4.trans.shared.b16 {%0,%1,%2,%3}, [%4];"
                    : "=r"(b[nt][0]), "=r"(b[nt][1]), "=r"(b[nt][2]), "=r"(b[nt][3])
                    : "r"(va));
            }
#pragma unroll
            for (int mt = 0; mt < 2; mt++)
#pragma unroll
                for (int nt = 0; nt < 4; nt++) {
                    MMA16816(acc[mt][2 * nt],     a[mt], b[nt][0], b[nt][1]);
                    MMA16816(acc[mt][2 * nt + 1], a[mt], b[nt][2], b[nt][3]);
                }
        }
    };

    // ---- prologue ----
    float4 lv0 = *(const float4*)(Lrow + 0);
    float4 lv1 = *(const float4*)(Lrow + 4);
    float4 lv2 = *(const float4*)(Lrow + 8);
    float4 lv3 = *(const float4*)(Lrow + 12);
    load_V(0);
    asm volatile("cp.async.commit_group;");
    load_V(1);
    asm volatile("cp.async.commit_group;");

    for (int c = 0; c < NCH; c++) {
        // prefetch L chunk c+1 into registers (full-interval latency cover)
        float4 nv0, nv1, nv2, nv3;
        if (c + 1 < NCH) {
            const float* Ln = Lrow + (size_t)(c + 1) * KT;
            nv0 = *(const float4*)(Ln + 0);
            nv1 = *(const float4*)(Ln + 4);
            nv2 = *(const float4*)(Ln + 8);
            nv3 = *(const float4*)(Ln + 12);
        }
        // prefetch V chunk c+2
        if (c + 2 < NCH) load_V(c + 2);
        asm volatile("cp.async.commit_group;");

        // ---- exp(c): registers -> P[c&1] (fp16, swizzled) ----
        {
            float e0 = __expf(lv0.x), e1 = __expf(lv0.y), e2 = __expf(lv0.z), e3 = __expf(lv0.w);
            float e4 = __expf(lv1.x), e5 = __expf(lv1.y), e6 = __expf(lv1.z), e7 = __expf(lv1.w);
            float e8 = __expf(lv2.x), e9 = __expf(lv2.y), ea = __expf(lv2.z), eb = __expf(lv2.w);
            float ec = __expf(lv3.x), ed = __expf(lv3.y), ee = __expf(lv3.z), ef = __expf(lv3.w);
            psum += ((e0 + e1) + (e2 + e3)) + ((e4 + e5) + (e6 + e7))
                  + ((e8 + e9) + (ea + eb)) + ((ec + ed) + (ee + ef));
            __half2 p0 = __floats2half2_rn(e0, e1), p1 = __floats2half2_rn(e2, e3);
            __half2 p2 = __floats2half2_rn(e4, e5), p3 = __floats2half2_rn(e6, e7);
            __half2 p4 = __floats2half2_rn(e8, e9), p5 = __floats2half2_rn(ea, eb);
            __half2 p6 = __floats2half2_rn(ec, ed), p7 = __floats2half2_rn(ee, ef);
            uint4 o0, o1;
            o0.x = *(uint32_t*)&p0; o0.y = *(uint32_t*)&p1;
            o0.z = *(uint32_t*)&p2; o0.w = *(uint32_t*)&p3;
            o1.x = *(uint32_t*)&p4; o1.y = *(uint32_t*)&p5;
            o1.z = *(uint32_t*)&p6; o1.w = *(uint32_t*)&p7;
            char* pr = smem + OFF_P + (c & 1) * 8192 + er * 64;
            *(uint4*)(pr + (((2 * eh + 0) ^ esp) << 4)) = o0;
            *(uint4*)(pr + (((2 * eh + 1) ^ esp) << 4)) = o1;
        }

        // ---- MMA(c-1): P[(c-1)&1] x V[(c-1)%4] ----
        if (c > 0) mma_chunk((c - 1) & 1, (c - 1) & (NV - 1));

        lv0 = nv0; lv1 = nv1; lv2 = nv2; lv3 = nv3;

        asm volatile("cp.async.wait_group 2;");
        __syncthreads();    // publishes P[c&1]; V stage + P buffer reuse safety
    }

    // ---- epilogue MMA: last chunk ----
    mma_chunk((NCH - 1) & 1, (NCH - 1) & (NV - 1));

    // rowsum: thread pair (t, t^1) shares row er
    {
        float v = psum + __shfl_xor_sync(0xffffffffu, psum, 1);
        if (eh == 0) rowsum[er] = v;
    }
    __syncthreads();

    // epilogue: O = acc / (rowsum + exp(sink))
    const float sinkv = __expf(sinks[h]);
#pragma unroll
    for (int mt = 0; mt < 2; mt++)
#pragma unroll
        for (int a2 = 0; a2 < 2; a2++) {
            int r = 32 * qw + 16 * mt + 8 * a2 + g;
            float inv = 1.0f / (rowsum[r] + sinkv);
            float* orow = out + ((size_t)h * SQ_ + q0 + r) * DH_ + 64 * nh + m * 2;
#pragma unroll
            for (int nt = 0; nt < 8; nt++) {
                float2 o;
                o.x = acc[mt][nt][2 * a2 + 0] * inv;
                o.y = acc[mt][nt][2 * a2 + 1] * inv;
                *(float2*)(orow + nt * 8) = o;
            }
        }
}

// ---------------- Launch ----------------
extern "C" void kernel_launch(void* const* d_in, const int* in_sizes, int n_in,
                              void* d_out, int out_size) {
    const float* logits = nullptr;
    const float* value  = nullptr;
    const float* sinks  = nullptr;
    for (int i = 0; i < n_in; i++) {
        if (in_sizes[i] == H_) sinks = (const float*)d_in[i];
        else if (in_sizes[i] == H_ * SQ_ * SK_) logits = (const float*)d_in[i];
        else if (in_sizes[i] == H_ * SK_ * DH_) value = (const float*)d_in[i];
    }
    float* out = (float*)d_out;

    convert_v_kernel<<<(H_ * SK_ * DH_) / (256 * 8), 256>>>(value);

    cudaFuncSetAttribute(attn_sink_kernel,
                         cudaFuncAttributeMaxDynamicSharedMemorySize, SMEM_SZ);
    attn_sink_kernel<<<H_ * (SQ_ / QT), 256, SMEM_SZ>>>(logits, sinks, out);
}

// round 10
// speedup vs baseline: 1.1306x; 1.1306x over previous
#include <cuda_runtime.h>
#include <cuda_fp16.h>
#include <cstdint>

#define H_  32
#define SQ_ 2048
#define SK_ 2048
#define DH_ 128
#define QT  128          // q rows per CTA
#define KT  32           // k per chunk
#define NCH (SK_/KT)     // 64 chunks
#define NV  4            // V pipeline stages

// SMEM layout (dynamic):
#define VSTAGE  8192                      // 32k x 128d fp16, xor-swizzled
#define OFF_P   (NV * VSTAGE)             // 32768  (P: 2 x 8192, 128 rows x 64B)
#define OFF_SUM (OFF_P + 2 * 8192)        // 49152
#define SMEM_SZ (OFF_SUM + 512)           // 49664

// V converted to fp16, natural [h][k][d] layout
__device__ alignas(16) __half g_vh[(size_t)H_ * SK_ * DH_];

__device__ __forceinline__ uint32_t smem_u32(const void* p) {
    uint32_t a;
    asm("{ .reg .u64 t; cvta.to.shared.u64 t, %1; cvt.u32.u64 %0, t; }" : "=r"(a) : "l"(p));
    return a;
}

#define MMA16816(D, A, B0, B1) \
    asm volatile( \
        "mma.sync.aligned.m16n8k16.row.col.f32.f16.f16.f32 " \
        "{%0,%1,%2,%3}, {%4,%5,%6,%7}, {%8,%9}, {%0,%1,%2,%3};" \
        : "+f"((D)[0]), "+f"((D)[1]), "+f"((D)[2]), "+f"((D)[3]) \
        : "r"((A)[0]), "r"((A)[1]), "r"((A)[2]), "r"((A)[3]), \
          "r"(B0), "r"(B1))

// ---------------- V fp32 -> fp16 convert ----------------
__global__ void convert_v_kernel(const float* __restrict__ v) {
    size_t i = ((size_t)blockIdx.x * 256 + threadIdx.x) * 8;
    float4 a = *(const float4*)(v + i);
    float4 b = *(const float4*)(v + i + 4);
    __half2 h0 = __floats2half2_rn(a.x, a.y);
    __half2 h1 = __floats2half2_rn(a.z, a.w);
    __half2 h2 = __floats2half2_rn(b.x, b.y);
    __half2 h3 = __floats2half2_rn(b.z, b.w);
    uint4 o;
    o.x = *(uint32_t*)&h0; o.y = *(uint32_t*)&h1;
    o.z = *(uint32_t*)&h2; o.w = *(uint32_t*)&h3;
    *(uint4*)(g_vh + i) = o;
}

// ---------------- Main fused kernel ----------------
// 256 threads = 8 warps. Warp w: q rows [32*(w&3), +32), n cols [64*(w>>2), +64).
// L: direct LDG.cg in granule mapping (thread t, u: row (t>>3)+32u, k (t&7)*4..+3).
// P layout: 128 rows x 64B (32 fp16), 16B-column swizzle c2 ^ ((row>>1)&3).
__global__ void __launch_bounds__(256, 2)
attn_sink_kernel(const float* __restrict__ logits,
                 const float* __restrict__ sinks,
                 float* __restrict__ out)
{
    extern __shared__ char smem[];
    float* rowsum = (float*)(smem + OFF_SUM);

    const int tid = threadIdx.x;
    const int w   = tid >> 5;
    const int l   = tid & 31;
    const int h   = blockIdx.x >> 4;
    const int q0  = (blockIdx.x & 15) * QT;

    const int qw = w & 3;      // q 32-group
    const int nh = w >> 2;     // n 64-half
    const int g  = l >> 2;     // acc row group
    const int m  = l & 3;      // acc col pair
    const int lu = l >> 4;
    const int kl = (l & 7) + 8 * ((l >> 3) & 1);

    const __half* Vh  = g_vh + (size_t)h * SK_ * DH_;
    const uint32_t vb = smem_u32(smem);

    // L granule mapping
    const int lr = tid >> 3;            // base row 0..31 (rows lr + 32u)
    const float* Lg = logits + ((size_t)h * SQ_ + q0 + lr) * SK_ + (tid & 7) * 4;

    // P store base: row = lr + 32u, swizzled 16B column
    const int s_sw = (tid >> 4) & 3;                 // (row>>1)&3, u-invariant
    const int c2p  = ((tid & 7) >> 1) ^ s_sw;
    char* Pst = smem + OFF_P + lr * 64 + c2p * 16 + (tid & 1) * 8;

    // A-ldmatrix per-lane addresses: lane l -> row R = 32qw+16mt+(l&15),
    // 16B col (2j + (l>>4)) ^ ((R>>1)&3)
    uint32_t aoff[2][2];   // [mt][j]
#pragma unroll
    for (int mt = 0; mt < 2; mt++) {
        int R = 32 * qw + 16 * mt + (l & 15);
        int s = (R >> 1) & 3;
#pragma unroll
        for (int j = 0; j < 2; j++)
            aoff[mt][j] = (uint32_t)(R * 64 + (((2 * j + lu) ^ s) << 4));
    }
    // B-ldmatrix precomputed per-ntile offsets (proven layout)
    uint32_t uB[4];
#pragma unroll
    for (int nt = 0; nt < 4; nt++) {
        int u = 8 * nh + 2 * nt + lu;
        uB[nt] = (uint32_t)(((u >> 3) << 12) + (((u & 7) ^ (l & 7)) << 4));
    }

    float acc[2][8][4];
#pragma unroll
    for (int mt = 0; mt < 2; mt++)
#pragma unroll
        for (int nt = 0; nt < 8; nt++)
#pragma unroll
            for (int c = 0; c < 4; c++) acc[mt][nt][c] = 0.f;
    float psum[4] = {0.f, 0.f, 0.f, 0.f};

    // V chunk loader: 32k x 16 granules = 512 / 256 thr = 2 each
    auto load_V = [&](int c) {
        const int s = c & (NV - 1);
#pragma unroll
        for (int u = 0; u < 2; u++) {
            int ci = u * 256 + tid;
            int k = ci >> 4, d = (ci & 15) * 8;
            uint32_t dst = vb + (uint32_t)(s * VSTAGE) + (uint32_t)((d >> 6) << 12)
                         + (uint32_t)(k << 7)
                         + (uint32_t)((((d >> 3) & 7) ^ (k & 7)) << 4);
            const __half* src = Vh + (size_t)(c * KT + k) * DH_ + d;
            asm volatile("cp.async.cg.shared.global [%0], [%1], 16;" :: "r"(dst), "l"(src));
        }
    };

    // MMA over one chunk: P[pbi] x V[vs]
    auto mma_chunk = [&](int pbi, int vs) {
        const uint32_t vst = vb + (uint32_t)(vs * VSTAGE);
        const uint32_t pba = vb + (uint32_t)(OFF_P + pbi * 8192);
#pragma unroll
        for (int j = 0; j < 2; j++) {
            uint32_t a[2][4];
#pragma unroll
            for (int mt = 0; mt < 2; mt++) {
                asm volatile(
                    "ldmatrix.sync.aligned.m8n8.x4.shared.b16 {%0,%1,%2,%3}, [%4];"
                    : "=r"(a[mt][0]), "=r"(a[mt][1]), "=r"(a[mt][2]), "=r"(a[mt][3])
                    : "r"(pba + aoff[mt][j]));
            }
            uint32_t b[4][4];
            const uint32_t rowoff = (uint32_t)((16 * j + kl) << 7);
#pragma unroll
            for (int nt = 0; nt < 4; nt++) {
                asm volatile(
                    "ldmatrix.sync.aligned.m8n8.x4.trans.shared.b16 {%0,%1,%2,%3}, [%4];"
                    : "=r"(b[nt][0]), "=r"(b[nt][1]), "=r"(b[nt][2]), "=r"(b[nt][3])
                    : "r"(vst + uB[nt] + rowoff));
            }
#pragma unroll
            for (int mt = 0; mt < 2; mt++)
#pragma unroll
                for (int nt = 0; nt < 4; nt++) {
                    MMA16816(acc[mt][2 * nt],     a[mt], b[nt][0], b[nt][1]);
                    MMA16816(acc[mt][2 * nt + 1], a[mt], b[nt][2], b[nt][3]);
                }
        }
    };

    // ---- prologue ----
    float4 lv[4];
#pragma unroll
    for (int u = 0; u < 4; u++)
        lv[u] = __ldcg((const float4*)(Lg + (size_t)u * 32 * SK_));
    load_V(0);
    asm volatile("cp.async.commit_group;");
    load_V(1);
    asm volatile("cp.async.commit_group;");

    for (int c = 0; c < NCH; c++) {
        // L prefetch chunk c+1 (coalesced, L2-only)
        float4 nv[4];
        if (c + 1 < NCH) {
            const float* Ln = Lg + (size_t)(c + 1) * KT;
#pragma unroll
            for (int u = 0; u < 4; u++)
                nv[u] = __ldcg((const float4*)(Ln + (size_t)u * 32 * SK_));
        }
        // V prefetch chunk c+2
        if (c + 2 < NCH) load_V(c + 2);
        asm volatile("cp.async.commit_group;");

        // ---- exp(c): registers -> P[c&1] ----
        {
            char* pb = Pst + (c & 1) * 8192;
#pragma unroll
            for (int u = 0; u < 4; u++) {
                float e0 = __expf(lv[u].x), e1 = __expf(lv[u].y);
                float e2 = __expf(lv[u].z), e3 = __expf(lv[u].w);
                psum[u] += (e0 + e1) + (e2 + e3);
                __half2 pa = __floats2half2_rn(e0, e1);
                __half2 pc = __floats2half2_rn(e2, e3);
                uint2 o;
                o.x = *(uint32_t*)&pa; o.y = *(uint32_t*)&pc;
                *(uint2*)(pb + u * 2048) = o;
            }
        }

        // ---- MMA(c-1) ----
        if (c > 0) mma_chunk((c - 1) & 1, (c - 1) & (NV - 1));

#pragma unroll
        for (int u = 0; u < 4; u++) lv[u] = nv[u];

        asm volatile("cp.async.wait_group 2;");
        __syncthreads();    // publishes P[c&1], V chunk c; guards ring reuse
    }

    // final chunk MMA
    mma_chunk((NCH - 1) & 1, (NCH - 1) & (NV - 1));

    // rowsum: 8 lanes (same tid>>3) share rows lr+32u
#pragma unroll
    for (int u = 0; u < 4; u++) {
        float v = psum[u];
        v += __shfl_xor_sync(0xffffffffu, v, 1);
        v += __shfl_xor_sync(0xffffffffu, v, 2);
        v += __shfl_xor_sync(0xffffffffu, v, 4);
        if ((l & 7) == 0) rowsum[lr + 32 * u] = v;
    }
    __syncthreads();

    // epilogue: O = acc / (rowsum + exp(sink))
    const float sinkv = __expf(sinks[h]);
#pragma unroll
    for (int mt = 0; mt < 2; mt++)
#pragma unroll
        for (int a2 = 0; a2 < 2; a2++) {
            int r = 32 * qw + 16 * mt + 8 * a2 + g;
            float inv = 1.0f / (rowsum[r] + sinkv);
            float* orow = out + ((size_t)h * SQ_ + q0 + r) * DH_ + 64 * nh + m * 2;
#pragma unroll
            for (int nt = 0; nt < 8; nt++) {
                float2 o;
                o.x = acc[mt][nt][2 * a2 + 0] * inv;
                o.y = acc[mt][nt][2 * a2 + 1] * inv;
                *(float2*)(orow + nt * 8) = o;
            }
        }
}

// ---------------- Launch ----------------
extern "C" void kernel_launch(void* const* d_in, const int* in_sizes, int n_in,
                              void* d_out, int out_size) {
    const float* logits = nullptr;
    const float* value  = nullptr;
    const float* sinks  = nullptr;
    for (int i = 0; i < n_in; i++) {
        if (in_sizes[i] == H_) sinks = (const float*)d_in[i];
        else if (in_sizes[i] == H_ * SQ_ * SK_) logits = (const float*)d_in[i];
        else if (in_sizes[i] == H_ * SK_ * DH_) value = (const float*)d_in[i];
    }
    float* out = (float*)d_out;

    convert_v_kernel<<<(H_ * SK_ * DH_) / (256 * 8), 256>>>(value);

    cudaFuncSetAttribute(attn_sink_kernel,
                         cudaFuncAttributeMaxDynamicSharedMemorySize, SMEM_SZ);
    attn_sink_kernel<<<H_ * (SQ_ / QT), 256, SMEM_SZ>>>(logits, sinks, out);
}